// round 13
// baseline (speedup 1.0000x reference)
#include <cuda_runtime.h>
#include <cuda_bf16.h>

#define N_NODES 50000
#define N_EDGES 800000
#define KPTS 15
#define IN_DIM 32
#define OUT_DIM 64
#define KP_EXT 0.6f
#define BIN_CAP 32768           // per-k pair capacity (expected max ~16.3K, 2x margin)
#define PB_BLOCKS_PER_K 29
#define PB_GRID (KPTS * PB_BLOCKS_PER_K)   // 435 blocks: one wave at 3 blocks/SM

// Sparse pair bins: per kernel-point k, packed {src|dst<<16, m_bits}.
__device__ float4 g_pos4[N_NODES];                       // 0.8 MB
__device__ uint2  g_bins[(size_t)KPTS * BIN_CAP];        // 3.9 MB (L2-resident)
__device__ int    g_cnt[KPTS];

// ---------------------------------------------------------------------------
// Prep: pack pos to float4, reset counters. (out is zeroed by memset node.)
// ---------------------------------------------------------------------------
__global__ __launch_bounds__(256) void k_prep(const float* __restrict__ pos) {
    int i = blockIdx.x * 256 + threadIdx.x;
    if (i < KPTS) g_cnt[i] = 0;
    if (i < N_NODES)
        g_pos4[i] = make_float4(__ldg(pos + 3 * i), __ldg(pos + 3 * i + 1),
                                __ldg(pos + 3 * i + 2), 0.f);
}

// ---------------------------------------------------------------------------
// Geometry: thread per edge. Ball test per kernel point (d^2 compare, no
// sqrt). Active (e,k) pairs binned by k: block-local smem counts -> one
// global atomicAdd per k per block -> scatter 8B packed entries.
// ---------------------------------------------------------------------------
__global__ __launch_bounds__(256) void k_geom(const float* __restrict__ kp,
                                              const int* __restrict__ esrc,
                                              const int* __restrict__ edst) {
    __shared__ float skp[KPTS * 3];
    __shared__ int scnt[KPTS], sbase[KPTS];
    int tid = threadIdx.x;
    if (tid < KPTS * 3) skp[tid] = __ldg(kp + tid);
    if (tid < KPTS) scnt[tid] = 0;
    __syncthreads();

    int e = blockIdx.x * 256 + tid;
    unsigned mask = 0;
    unsigned src = 0, dst = 0;
    float y0 = 0.f, y1 = 0.f, y2 = 0.f;
    if (e < N_EDGES) {
        src = (unsigned)__ldg(esrc + e);
        dst = (unsigned)__ldg(edst + e);
        float4 ps = g_pos4[src], pd = g_pos4[dst];
        y0 = ps.x - pd.x; y1 = ps.y - pd.y; y2 = ps.z - pd.z;
        #pragma unroll
        for (int k = 0; k < KPTS; k++) {
            float d0 = y0 - skp[3 * k], d1 = y1 - skp[3 * k + 1], d2 = y2 - skp[3 * k + 2];
            if (d0 * d0 + d1 * d1 + d2 * d2 < KP_EXT * KP_EXT) mask |= (1u << k);
        }
    }

    unsigned mm = mask;
    while (mm) { int k = __ffs(mm) - 1; mm &= mm - 1; atomicAdd(&scnt[k], 1); }
    __syncthreads();
    if (tid < KPTS) { sbase[tid] = atomicAdd(&g_cnt[tid], scnt[tid]); scnt[tid] = 0; }
    __syncthreads();

    mm = mask;
    while (mm) {
        int k = __ffs(mm) - 1; mm &= mm - 1;
        int slot = sbase[k] + atomicAdd(&scnt[k], 1);
        if (slot < BIN_CAP) {
            float d0 = y0 - skp[3 * k], d1 = y1 - skp[3 * k + 1], d2 = y2 - skp[3 * k + 2];
            float m = 1.f - sqrtf(d0 * d0 + d1 * d1 + d2 * d2) * (1.f / KP_EXT);
            if (m < 0.f) m = 0.f;
            g_bins[(size_t)k * BIN_CAP + slot] =
                make_uint2(src | (dst << 16), __float_as_uint(m));
        }
    }
}

// ---------------------------------------------------------------------------
// Apply: block group per kernel point; W_k (8KB) smem-resident, reused across
// the bin. Warp processes 4 pairs per pass. Lane = h*16 + c4 owns cols
// 4*c4..+3, i-half h. Inner loop: 3x LDS.128 + 8x FFMA2 per i.
// 3-stage pipeline: entries for passes n+1,n+2 held in regs; at pass n we
// issue bin[n+2] and feat-for-(n+1), so each L2 hop (~234cyc) has a full
// pass of compute to hide under. Sentinel entries (m=0, row 0) keep every
// branch warp-uniform. Halves combined by shfl_xor(16); h==0 lanes emit one
// red.global.add.v4.f32 per pair (skipped for m<=0).
// ---------------------------------------------------------------------------
__global__ __launch_bounds__(256, 3) void k_apply(const float* __restrict__ W,
                                                  const float* __restrict__ feat,
                                                  float* __restrict__ out) {
    __shared__ __align__(16) float4 sW[IN_DIM * 16];        // [i][c4] : 8 KB
    __shared__ ulonglong2 sFd[2][8][32];                    // dup-f: 8 KB

    int k = blockIdx.x / PB_BLOCKS_PER_K;
    int blkInK = blockIdx.x - k * PB_BLOCKS_PER_K;
    int tid = threadIdx.x;

    const float4* Wk = (const float4*)(W + (size_t)k * IN_DIM * OUT_DIM);
    sW[tid]       = __ldg(Wk + tid);
    sW[tid + 256] = __ldg(Wk + tid + 256);
    __syncthreads();

    int cnt = g_cnt[k];
    cnt = (cnt < BIN_CAP) ? cnt : BIN_CAP;
    if (cnt <= 0) return;

    int lane = tid & 31, wl = tid >> 5;
    int h = lane >> 4, c4 = lane & 15;
    const uint2* bin = g_bins + (size_t)k * BIN_CAP;
    const ulonglong2* sW2 = (const ulonglong2*)sW;
    const int STRIDE = PB_BLOCKS_PER_K * 8 * 4;
    int base = (blkInK * 8 + wl) * 4;

    // E0 = entries for current pass, E1 = next pass, F0 = feats for current.
    uint2 E0[4], E1[4];
    float F0[4], F1[4];
    #pragma unroll
    for (int p = 0; p < 4; p++) {
        int i0 = base + p, i1 = base + STRIDE + p;
        E0[p] = (i0 < cnt) ? __ldg(bin + i0) : make_uint2(0u, 0u);
        E1[p] = (i1 < cnt) ? __ldg(bin + i1) : make_uint2(0u, 0u);
    }
    #pragma unroll
    for (int p = 0; p < 4; p++) {
        unsigned sp = E0[p].x & 0xFFFFu;
        F0[p] = __ldg(feat + (size_t)sp * IN_DIM + lane) * __uint_as_float(E0[p].y);
    }

    for (; base < cnt; base += STRIDE) {
        // ---- stage pre-duplicated f: 2 conflict-free STS.128 ----
        ulonglong2 v0, v1;
        asm("mov.b64 %0, {%1,%1};" : "=l"(v0.x) : "r"(__float_as_uint(F0[0])));
        asm("mov.b64 %0, {%1,%1};" : "=l"(v0.y) : "r"(__float_as_uint(F0[1])));
        asm("mov.b64 %0, {%1,%1};" : "=l"(v1.x) : "r"(__float_as_uint(F0[2])));
        asm("mov.b64 %0, {%1,%1};" : "=l"(v1.y) : "r"(__float_as_uint(F0[3])));
        sFd[0][wl][lane] = v0;
        sFd[1][wl][lane] = v1;
        __syncwarp();

        // ---- pipeline: issue bin[n+2] and feat for E1 (loaded last pass) --
        uint2 E2[4];
        #pragma unroll
        for (int p = 0; p < 4; p++) {
            int i2 = base + 2 * STRIDE + p;
            E2[p] = (i2 < cnt) ? __ldg(bin + i2) : make_uint2(0u, 0u);
        }
        #pragma unroll
        for (int p = 0; p < 4; p++) {
            unsigned sp = E1[p].x & 0xFFFFu;
            F1[p] = __ldg(feat + (size_t)sp * IN_DIM + lane) * __uint_as_float(E1[p].y);
        }

        // ---- compute: per i = 3 LDS.128 + 8 FFMA2, no movs ----
        unsigned long long a01[4] = {0,0,0,0}, a23[4] = {0,0,0,0};
        #pragma unroll
        for (int s = 0; s < 16; s++) {
            int i = s + 16 * h;
            ulonglong2 w   = sW2[i * 16 + c4];      // (w0,w1),(w2,w3) packed
            ulonglong2 G01 = sFd[0][wl][i];         // (f0,f0),(f1,f1)
            ulonglong2 G23 = sFd[1][wl][i];         // (f2,f2),(f3,f3)
            asm("fma.rn.f32x2 %0, %1, %2, %0;" : "+l"(a01[0]) : "l"(G01.x), "l"(w.x));
            asm("fma.rn.f32x2 %0, %1, %2, %0;" : "+l"(a23[0]) : "l"(G01.x), "l"(w.y));
            asm("fma.rn.f32x2 %0, %1, %2, %0;" : "+l"(a01[1]) : "l"(G01.y), "l"(w.x));
            asm("fma.rn.f32x2 %0, %1, %2, %0;" : "+l"(a23[1]) : "l"(G01.y), "l"(w.y));
            asm("fma.rn.f32x2 %0, %1, %2, %0;" : "+l"(a01[2]) : "l"(G23.x), "l"(w.x));
            asm("fma.rn.f32x2 %0, %1, %2, %0;" : "+l"(a23[2]) : "l"(G23.x), "l"(w.y));
            asm("fma.rn.f32x2 %0, %1, %2, %0;" : "+l"(a01[3]) : "l"(G23.y), "l"(w.x));
            asm("fma.rn.f32x2 %0, %1, %2, %0;" : "+l"(a23[3]) : "l"(G23.y), "l"(w.y));
        }
        __syncwarp();   // sFd reads done before next pass overwrites

        // ---- reduce halves + REDG ----
        #pragma unroll
        for (int p = 0; p < 4; p++) {
            if (!(__uint_as_float(E0[p].y) > 0.f)) continue;  // warp-uniform
            int dstN = (int)(E0[p].x >> 16);
            unsigned x0, x1, x2, x3;
            asm("mov.b64 {%0,%1}, %2;" : "=r"(x0), "=r"(x1) : "l"(a01[p]));
            asm("mov.b64 {%0,%1}, %2;" : "=r"(x2), "=r"(x3) : "l"(a23[p]));
            float v0f = __uint_as_float(x0), v1f = __uint_as_float(x1);
            float v2f = __uint_as_float(x2), v3f = __uint_as_float(x3);
            v0f += __shfl_xor_sync(0xffffffffu, v0f, 16);
            v1f += __shfl_xor_sync(0xffffffffu, v1f, 16);
            v2f += __shfl_xor_sync(0xffffffffu, v2f, 16);
            v3f += __shfl_xor_sync(0xffffffffu, v3f, 16);
            if (h == 0) {
                float* dp = out + (size_t)dstN * OUT_DIM + c4 * 4;
                asm volatile("red.global.add.v4.f32 [%0], {%1,%2,%3,%4};"
                             :: "l"(dp), "f"(v0f), "f"(v1f), "f"(v2f), "f"(v3f)
                             : "memory");
            }
        }

        // ---- rotate pipeline ----
        #pragma unroll
        for (int p = 0; p < 4; p++) { E0[p] = E1[p]; E1[p] = E2[p]; F0[p] = F1[p]; }
    }
}

extern "C" void kernel_launch(void* const* d_in, const int* in_sizes, int n_in,
                              void* d_out, int out_size) {
    const float* pos  = (const float*)d_in[0];
    const float* feat = (const float*)d_in[1];
    const float* kp   = (const float*)d_in[2];
    const float* W    = (const float*)d_in[3];
    const int*   esrc = (const int*)d_in[4];
    const int*   edst = (const int*)d_in[5];
    float* out = (float*)d_out;

    cudaMemsetAsync(out, 0, (size_t)out_size * sizeof(float));
    k_prep<<<(N_NODES + 255) / 256, 256>>>(pos);
    k_geom<<<(N_EDGES + 255) / 256, 256>>>(kp, esrc, edst);
    k_apply<<<PB_GRID, 256>>>(W, feat, out);
}